// round 2
// baseline (speedup 1.0000x reference)
#include <cuda_runtime.h>

#define NN 100000
#define NE 1600000
#define NF 256
#define NH 128
#define NC 8

// Scratch (static __device__ — no runtime allocation allowed)
__device__ __align__(16) float d_g[NN * NC];     // g = X @ Wc, L2-resident (3.2 MB)
__device__ float d_dinv[NN];
__device__ int   d_deg[NN];
__device__ __align__(16) float d_Wc[NF * NC];    // W1 @ Wfc
__device__ __align__(16) float d_bc[NC];         // b1 @ Wfc + bfc

// Detect whether edge_index is int64 (every odd 32-bit word == 0) or int32.
__device__ __forceinline__ bool ei_is64(const int* __restrict__ ei32) {
    return (__ldg(ei32 + 1) == 0) && (__ldg(ei32 + 3) == 0);
}
// Fetch index #i from a logical [2*NE] index array under either dtype.
__device__ __forceinline__ int ei_get(const int* __restrict__ ei32, bool is64, int i) {
    return is64 ? __ldg(ei32 + 2 * i) : __ldg(ei32 + i);   // little-endian low word
}

// ---------------- fold the two linear layers ----------------
__global__ void k_fold(const float* __restrict__ W1, const float* __restrict__ b1,
                       const float* __restrict__ Wfc, const float* __restrict__ bfc) {
    int idx = blockIdx.x * blockDim.x + threadIdx.x;
    if (idx < NF * NC) {
        int k = idx >> 3, c = idx & 7;
        float s = 0.f;
        #pragma unroll 8
        for (int j = 0; j < NH; j++) s = fmaf(W1[k * NH + j], Wfc[j * NC + c], s);
        d_Wc[idx] = s;
    }
    if (idx < NC) {
        float s = bfc[idx];
        for (int j = 0; j < NH; j++) s = fmaf(b1[j], Wfc[j * NC + idx], s);
        d_bc[idx] = s;
    }
}

// ---------------- degree (in-degree by dst, +1 self-loop) ----------------
__global__ void k_deg_init() {
    int i = blockIdx.x * blockDim.x + threadIdx.x;
    if (i < NN) d_deg[i] = 1;   // self-loop
}

__global__ void k_deg(const int* __restrict__ ei32) {
    int e = blockIdx.x * blockDim.x + threadIdx.x;
    if (e >= NE) return;
    bool is64 = ei_is64(ei32);
    int d = ei_get(ei32, is64, NE + e);
    atomicAdd(&d_deg[d], 1);
}

__global__ void k_dinv() {
    int i = blockIdx.x * blockDim.x + threadIdx.x;
    if (i < NN) d_dinv[i] = rsqrtf((float)d_deg[i]);
}

// ---------------- g = X @ Wc : warp per row, Wc in registers ----------------
__global__ void k_xw(const float* __restrict__ x) {
    int lane = threadIdx.x & 31;
    int warp_global = (blockIdx.x * blockDim.x + threadIdx.x) >> 5;
    int nwarps = (gridDim.x * blockDim.x) >> 5;

    // Each lane owns k = lane*8 .. lane*8+7 of the 256-dim reduction.
    float w[8][NC];
    #pragma unroll
    for (int t = 0; t < 8; t++) {
        float4 w0 = ((const float4*)d_Wc)[(lane * 8 + t) * 2];
        float4 w1 = ((const float4*)d_Wc)[(lane * 8 + t) * 2 + 1];
        w[t][0] = w0.x; w[t][1] = w0.y; w[t][2] = w0.z; w[t][3] = w0.w;
        w[t][4] = w1.x; w[t][5] = w1.y; w[t][6] = w1.z; w[t][7] = w1.w;
    }

    for (int row = warp_global; row < NN; row += nwarps) {
        const float4* xr = (const float4*)(x + (size_t)row * NF);
        float4 a = xr[lane * 2];
        float4 b = xr[lane * 2 + 1];
        float xs[8] = {a.x, a.y, a.z, a.w, b.x, b.y, b.z, b.w};

        float acc[NC];
        #pragma unroll
        for (int c = 0; c < NC; c++) acc[c] = 0.f;
        #pragma unroll
        for (int t = 0; t < 8; t++)
            #pragma unroll
            for (int c = 0; c < NC; c++) acc[c] = fmaf(xs[t], w[t][c], acc[c]);

        #pragma unroll
        for (int off = 16; off; off >>= 1)
            #pragma unroll
            for (int c = 0; c < NC; c++)
                acc[c] += __shfl_down_sync(0xffffffffu, acc[c], off);

        if (lane == 0) {
            float4* o = (float4*)(d_g + (size_t)row * NC);
            o[0] = make_float4(acc[0], acc[1], acc[2], acc[3]);
            o[1] = make_float4(acc[4], acc[5], acc[6], acc[7]);
        }
    }
}

// ---------------- out init: bias + self-loop term ----------------
__global__ void k_self(float* __restrict__ out) {
    int i = blockIdx.x * blockDim.x + threadIdx.x;
    if (i >= NN) return;
    float dv = d_dinv[i];
    float wgt = dv * dv;
    float4 g0 = ((const float4*)d_g)[i * 2];
    float4 g1 = ((const float4*)d_g)[i * 2 + 1];
    float4 b0 = ((const float4*)d_bc)[0];
    float4 b1v = ((const float4*)d_bc)[1];
    ((float4*)out)[i * 2] = make_float4(b0.x + wgt * g0.x, b0.y + wgt * g0.y,
                                        b0.z + wgt * g0.z, b0.w + wgt * g0.w);
    ((float4*)out)[i * 2 + 1] = make_float4(b1v.x + wgt * g1.x, b1v.y + wgt * g1.y,
                                            b1v.z + wgt * g1.z, b1v.w + wgt * g1.w);
}

// ---------------- edge aggregation: 2 lanes/edge, v4 RED into L2 ----------------
__global__ void k_edges(const int* __restrict__ ei32, float* __restrict__ out) {
    int t = blockIdx.x * blockDim.x + threadIdx.x;
    int e = t >> 1;
    int half = t & 1;
    if (e >= NE) return;
    bool is64 = ei_is64(ei32);
    int s = ei_get(ei32, is64, e);
    int d = ei_get(ei32, is64, NE + e);
    float norm = d_dinv[s] * d_dinv[d];
    float4 gv = ((const float4*)d_g)[s * 2 + half];
    float4* op = ((float4*)out) + d * 2 + half;
    asm volatile("red.global.add.v4.f32 [%0], {%1, %2, %3, %4};"
                 :: "l"(op),
                    "f"(gv.x * norm), "f"(gv.y * norm),
                    "f"(gv.z * norm), "f"(gv.w * norm)
                 : "memory");
}

extern "C" void kernel_launch(void* const* d_in, const int* in_sizes, int n_in,
                              void* d_out, int out_size) {
    const float* x      = (const float*)d_in[0];
    const int*   ei32   = (const int*)d_in[1];   // [2, NE], int32 or int64 (auto-detected)
    const float* W1     = (const float*)d_in[2];
    const float* b1     = (const float*)d_in[3];
    const float* Wfc    = (const float*)d_in[4];
    const float* bfc    = (const float*)d_in[5];
    float* out          = (float*)d_out;

    k_fold<<<(NF * NC + 255) / 256, 256>>>(W1, b1, Wfc, bfc);
    k_deg_init<<<(NN + 255) / 256, 256>>>();
    k_deg<<<(NE + 255) / 256, 256>>>(ei32);
    k_dinv<<<(NN + 255) / 256, 256>>>();
    k_xw<<<592, 256>>>(x);
    k_self<<<(NN + 255) / 256, 256>>>(out);
    k_edges<<<(NE * 2 + 255) / 256, 256>>>(ei32, out);
}